// round 5
// baseline (speedup 1.0000x reference)
#include <cuda_runtime.h>

// LFR constants from the reference: M=7, N=6, LEFT=ceil((M-1)//2)=3, D=80.
#define MM 7
#define NN 6
#define LEFTP 3
#define DD 80
#define F4_PER_FRAME 20   /* 80/4  */
#define F4_PER_ROW   140  /* 7*20  */

#define MAXB 1024
__device__ int g_limit[MAXB];  // 3 + lens[b]
__device__ int g_fb[MAXB];     // fallback source frame for t >= limit

// One block, B threads (B <= 1024). Computes per-batch right_pad / T_all,
// reduces T_all_max across the batch, derives the fallback frame, and
// writes new_len (as float) if the output buffer carries it.
__global__ void lfr_prep_kernel(const int* __restrict__ lens,
                                float* __restrict__ newlen_out,
                                int T, int B, int write_newlen) {
    __shared__ int s_tall[MAXB];
    int b = threadIdx.x;
    int L = 1, T_all = 0;
    if (b < B) {
        L = lens[b];
        int c6    = (L + (NN - 1)) / NN;          // ceil(L/6)
        int delta = L + LEFTP + NN - NN * c6;     // L + 9 - 6*ceil(L/6)
        int rp    = MM - delta; if (rp < 0) rp = 0;
        T_all     = LEFTP + L + rp;
        if (write_newlen) newlen_out[b] = (float)(T_all / NN);
        g_limit[b] = LEFTP + L;
    }
    s_tall[b] = T_all;
    __syncthreads();
    for (int s = blockDim.x >> 1; s > 0; s >>= 1) {
        if (b < s) s_tall[b] = max(s_tall[b], s_tall[b + s]);
        __syncthreads();
    }
    int Tmax = s_tall[0];
    int jmax = Tmax - 1;  // padded index used for masked-out positions
    if (b < B) {
        // padded[j]: j<3 -> frame 0 ; 3<=j<3+T -> frame j-3 ; else -> frame L-1
        g_fb[b] = (jmax < LEFTP + T) ? (jmax - LEFTP) : (L - 1);
    }
}

// One float4 of output per thread. blockIdx.y = batch.
// out[b, f, m*80+d] = x[b, src(f*6+m), d]
__global__ void lfr_gather_kernel(const float4* __restrict__ x4,
                                  float4* __restrict__ out4,
                                  int T, int nf) {
    int b = blockIdx.y;
    int total = nf * F4_PER_ROW;
    int i = blockIdx.x * blockDim.x + threadIdx.x;
    if (i >= total) return;

    int limit = g_limit[b];
    int fb    = g_fb[b];

    int f = i / F4_PER_ROW;
    int r = i - f * F4_PER_ROW;
    int m = r / F4_PER_FRAME;
    int k = r - m * F4_PER_FRAME;

    int t   = f * NN + m;
    int tm3 = t - LEFTP;
    int src = (t < limit) ? (tm3 < 0 ? 0 : tm3) : fb;

    out4[(size_t)b * total + i] =
        x4[((size_t)b * T + src) * F4_PER_FRAME + k];
}

extern "C" void kernel_launch(void* const* d_in, const int* in_sizes, int n_in,
                              void* d_out, int out_size) {
    const float* x    = (const float*)d_in[0];
    const int*   lens = (const int*)d_in[1];

    int B = in_sizes[1];                 // 64
    int T = in_sizes[0] / (B * DD);      // 4096

    long long per = (long long)B * (MM * DD);  // elems per output frame-row across batch
    long long nf;
    int write_newlen = 0;
    if (out_size > B && ((long long)(out_size - B) % per) == 0) {
        write_newlen = 1;
        nf = ((long long)out_size - B) / per;
    } else {
        nf = (long long)out_size / per;
    }

    float* out    = (float*)d_out;
    float* newlen = out + (long long)B * nf * (MM * DD);

    lfr_prep_kernel<<<1, B>>>(lens, newlen, T, B, write_newlen);

    int total = (int)nf * F4_PER_ROW;
    dim3 grid((total + 255) / 256, B);
    lfr_gather_kernel<<<grid, 256>>>((const float4*)x, (float4*)out, T, (int)nf);
}

// round 6
// speedup vs baseline: 1.1649x; 1.1649x over previous
#include <cuda_runtime.h>

// LFR: M=7, N=6, LEFT=3, D=80 floats = 20 float4 per frame, 140 float4 per output row.
#define MM 7
#define NN 6
#define LEFTP 3
#define DD 80
#define F4F 20    /* float4 per frame */
#define F4R 140   /* float4 per row (7 frames) */
#define RPB 4     /* rows per block */
#define TPB 160   /* threads per block (5 warps, j<140 active) */

__device__ __forceinline__ int t_all_of(int L) {
    int c6    = (L + 5) / 6;          // ceil(L/6)
    int delta = L + 9 - 6 * c6;       // prepad - N*(n_lfr-1)
    int rp    = 7 - delta; if (rp < 0) rp = 0;
    return 3 + L + rp;
}

// grid = (ceil(nf/RPB), B), block = TPB.
// out[b, f, m*80+d] = x[b, src(6f+m), d];  src = (t<L+3) ? max(t-3,0) : fb
// fb = (Tmax-1 < 3+T) ? Tmax-4 : L-1, Tmax = max_b T_all(lens[b]).
__global__ __launch_bounds__(TPB)
void lfr_fused_kernel(const float4* __restrict__ x4,
                      float4* __restrict__ out4,
                      const int* __restrict__ lens,
                      float* __restrict__ newlen,
                      int T, int nf, int B, int write_newlen) {
    const int b  = blockIdx.y;
    const int f0 = blockIdx.x * RPB;
    const int j  = threadIdx.x;

    const int L     = __ldg(&lens[b]);
    const int limit = L + LEFTP;

    // Per-batch new_len written once, by block (0, b).
    if (write_newlen && blockIdx.x == 0 && j == 0)
        newlen[b] = (float)(t_all_of(L) / NN);

    // Does this block contain any row touching t >= limit (needs fb)?
    const int fLast   = min(f0 + RPB - 1, nf - 1);
    const bool need_fb = (NN * fLast + NN) >= limit;   // block-uniform

    __shared__ int s_max[TPB / 32];
    int fb = 0;
    if (need_fb) {
        // Tmax = max over batch of T_all (lens[] is tiny and L2-hot).
        int v = 0;
        if (j < B) v = t_all_of(__ldg(&lens[j]));
        #pragma unroll
        for (int off = 16; off; off >>= 1)
            v = max(v, __shfl_xor_sync(0xffffffffu, v, off));
        if ((j & 31) == 0) s_max[j >> 5] = v;
        __syncthreads();
        int Tmax = s_max[0];
        #pragma unroll
        for (int w = 1; w < TPB / 32; w++) Tmax = max(Tmax, s_max[w]);
        const int jmax = Tmax - 1;                     // padded index for masked slots
        fb = (jmax < LEFTP + T) ? (jmax - LEFTP) : (L - 1);
    }

    const bool active = (j < F4R);
    const size_t xb = (size_t)b * T * F4F;                       // x4 base for batch
    const size_t ob = ((size_t)b * nf + f0) * F4R + j;           // out4 base (row f0)

    float4 v[RPB];
    bool   ok[RPB];

    #pragma unroll
    for (int r = 0; r < RPB; r++) {
        const int f = f0 + r;
        ok[r] = active && (f < nf);
        if (!ok[r]) continue;
        int src_f4;
        if (f >= 1 && (NN * f + NN) < limit) {
            // Fast path: whole row is a contiguous slice of x.
            src_f4 = (NN * f - LEFTP) * F4F + j;
        } else {
            // Slow path: per-element clamp / fallback.
            const int m   = (j * 205) >> 12;                     // exact j/20 for j<140
            const int t   = NN * f + m;
            const int tm3 = t - LEFTP;
            const int src = (t < limit) ? (tm3 < 0 ? 0 : tm3) : fb;
            src_f4 = src * F4F + (j - m * F4F);
        }
        v[r] = __ldg(&x4[xb + src_f4]);
    }

    #pragma unroll
    for (int r = 0; r < RPB; r++)
        if (ok[r]) out4[ob + (size_t)r * F4R] = v[r];
}

extern "C" void kernel_launch(void* const* d_in, const int* in_sizes, int n_in,
                              void* d_out, int out_size) {
    const float* x    = (const float*)d_in[0];
    const int*   lens = (const int*)d_in[1];

    int B = in_sizes[1];                 // 64
    int T = in_sizes[0] / (B * DD);      // 4096

    long long per = (long long)B * (MM * DD);   // output elems per frame-row across batch
    long long nf;
    int write_newlen = 0;
    if (out_size > B && ((long long)(out_size - B) % per) == 0) {
        write_newlen = 1;
        nf = ((long long)out_size - B) / per;
    } else {
        nf = (long long)out_size / per;
    }

    float* out    = (float*)d_out;
    float* newlen = out + (long long)B * nf * (MM * DD);

    dim3 grid(((int)nf + RPB - 1) / RPB, B);
    lfr_fused_kernel<<<grid, TPB>>>((const float4*)x, (float4*)out,
                                    lens, newlen, T, (int)nf, B, write_newlen);
}